// round 1
// baseline (speedup 1.0000x reference)
#include <cuda_runtime.h>
#include <math.h>

#define N_ROWS   8192
#define F_IN     512
#define H_DIM    256
#define W_DIM    64
#define R_PER_BLK 16
#define NBLK     (N_ROWS / R_PER_BLK)   // 512
#define THREADS  256

// Per-block column partial sums (deterministic two-stage reduction, no atomics).
__device__ float g_part[NBLK * W_DIM];

__global__ __launch_bounds__(THREADS, 4)
void fused_mlp_kernel(const float* __restrict__ X,
                      const float* __restrict__ W1, const float* __restrict__ b1,
                      const float* __restrict__ W2, const float* __restrict__ b2,
                      const float* __restrict__ Wq, const float* __restrict__ bq)
{
    // Region A: X tile (16x512 f32 = 32KB), later reused as enc2 (16x256).
    // Region B: enc1 (16x256 f32 = 16KB), later reused for column partials.
    __shared__ float sA[R_PER_BLK * F_IN];
    __shared__ float sB[R_PER_BLK * H_DIM];

    const int t = threadIdx.x;
    const int row0 = blockIdx.x * R_PER_BLK;

    // ---- Phase 0: load X tile (contiguous 16*512 floats), float4 coalesced ----
    {
        const float4* Xg = reinterpret_cast<const float4*>(X + (size_t)row0 * F_IN);
        float4* Xs = reinterpret_cast<float4*>(sA);
        #pragma unroll
        for (int i = t; i < R_PER_BLK * F_IN / 4; i += THREADS)
            Xs[i] = Xg[i];
    }
    __syncthreads();

    // ---- Phase 1: enc1 = relu(X @ W1 + b1); thread t owns column j=t ----
    {
        const int j = t;
        float acc[R_PER_BLK];
        const float bj = b1[j];
        #pragma unroll
        for (int r = 0; r < R_PER_BLK; r++) acc[r] = bj;

        for (int k = 0; k < F_IN; k += 4) {
            const float w0 = W1[(k + 0) * H_DIM + j];
            const float w1 = W1[(k + 1) * H_DIM + j];
            const float w2 = W1[(k + 2) * H_DIM + j];
            const float w3 = W1[(k + 3) * H_DIM + j];
            #pragma unroll
            for (int r = 0; r < R_PER_BLK; r++) {
                float4 x = *reinterpret_cast<const float4*>(&sA[r * F_IN + k]);
                acc[r] = fmaf(x.x, w0, acc[r]);
                acc[r] = fmaf(x.y, w1, acc[r]);
                acc[r] = fmaf(x.z, w2, acc[r]);
                acc[r] = fmaf(x.w, w3, acc[r]);
            }
        }
        #pragma unroll
        for (int r = 0; r < R_PER_BLK; r++)
            sB[r * H_DIM + j] = fmaxf(acc[r], 0.0f);
    }
    __syncthreads();   // enc1 ready; all reads of X-tile (sA) complete

    // ---- Phase 2: enc2 = relu(enc1 @ W2 + b2) -> written into region A ----
    {
        const int j = t;
        float acc[R_PER_BLK];
        const float bj = b2[j];
        #pragma unroll
        for (int r = 0; r < R_PER_BLK; r++) acc[r] = bj;

        for (int k = 0; k < H_DIM; k += 4) {
            const float w0 = W2[(k + 0) * H_DIM + j];
            const float w1 = W2[(k + 1) * H_DIM + j];
            const float w2 = W2[(k + 2) * H_DIM + j];
            const float w3 = W2[(k + 3) * H_DIM + j];
            #pragma unroll
            for (int r = 0; r < R_PER_BLK; r++) {
                float4 e = *reinterpret_cast<const float4*>(&sB[r * H_DIM + k]);
                acc[r] = fmaf(e.x, w0, acc[r]);
                acc[r] = fmaf(e.y, w1, acc[r]);
                acc[r] = fmaf(e.z, w2, acc[r]);
                acc[r] = fmaf(e.w, w3, acc[r]);
            }
        }
        #pragma unroll
        for (int r = 0; r < R_PER_BLK; r++)
            sA[r * H_DIM + j] = fmaxf(acc[r], 0.0f);   // enc2 in region A
    }
    __syncthreads();   // enc2 ready; all reads of enc1 (sB) complete

    // ---- Phase 3: q = tanh(enc2 @ Wq + bq); per-block column sums ----
    {
        const int c  = t & (W_DIM - 1);   // 0..63
        const int rg = t >> 6;            // 0..3 -> rows rg*4 .. rg*4+3
        float acc[4];
        const float bc = bq[c];
        #pragma unroll
        for (int i = 0; i < 4; i++) acc[i] = bc;

        for (int k = 0; k < H_DIM; k += 4) {
            const float w0 = Wq[(k + 0) * W_DIM + c];
            const float w1 = Wq[(k + 1) * W_DIM + c];
            const float w2 = Wq[(k + 2) * W_DIM + c];
            const float w3 = Wq[(k + 3) * W_DIM + c];
            #pragma unroll
            for (int i = 0; i < 4; i++) {
                const int r = rg * 4 + i;
                float4 e = *reinterpret_cast<const float4*>(&sA[r * H_DIM + k]);
                acc[i] = fmaf(e.x, w0, acc[i]);
                acc[i] = fmaf(e.y, w1, acc[i]);
                acc[i] = fmaf(e.z, w2, acc[i]);
                acc[i] = fmaf(e.w, w3, acc[i]);
            }
        }
        const float s = tanhf(acc[0]) + tanhf(acc[1]) + tanhf(acc[2]) + tanhf(acc[3]);
        sB[rg * W_DIM + c] = s;   // region B reused (enc1 dead)
    }
    __syncthreads();

    if (t < W_DIM) {
        const float v = sB[t] + sB[W_DIM + t] + sB[2 * W_DIM + t] + sB[3 * W_DIM + t];
        g_part[blockIdx.x * W_DIM + t] = v;
    }
}

// Reduce 512x64 partials, dot with Wh, add bh -> scalar out.
__global__ void reduce_kernel(const float* __restrict__ Wh,
                              const float* __restrict__ bh,
                              float* __restrict__ out)
{
    __shared__ float sp[4 * W_DIM];
    const int t = threadIdx.x;
    const int c = t & (W_DIM - 1);
    const int q = t >> 6;   // 0..3

    float s = 0.0f;
    for (int b = q; b < NBLK; b += 4)
        s += g_part[b * W_DIM + c];
    sp[q * W_DIM + c] = s;
    __syncthreads();

    if (t == 0) {
        float tot = bh[0];
        #pragma unroll
        for (int cc = 0; cc < W_DIM; cc++) {
            const float agg = sp[cc] + sp[W_DIM + cc] + sp[2 * W_DIM + cc] + sp[3 * W_DIM + cc];
            tot = fmaf(agg, Wh[cc], tot);
        }
        out[0] = tot;
    }
}

extern "C" void kernel_launch(void* const* d_in, const int* in_sizes, int n_in,
                              void* d_out, int out_size)
{
    const float* X  = (const float*)d_in[0];
    const float* W1 = (const float*)d_in[1];
    const float* b1 = (const float*)d_in[2];
    const float* W2 = (const float*)d_in[3];
    const float* b2 = (const float*)d_in[4];
    const float* Wq = (const float*)d_in[5];
    const float* bq = (const float*)d_in[6];
    const float* Wh = (const float*)d_in[7];
    const float* bh = (const float*)d_in[8];

    fused_mlp_kernel<<<NBLK, THREADS>>>(X, W1, b1, W2, b2, Wq, bq);
    reduce_kernel<<<1, THREADS>>>(Wh, bh, (float*)d_out);
}

// round 2
// speedup vs baseline: 1.1144x; 1.1144x over previous
#include <cuda_runtime.h>
#include <math.h>

#define N_ROWS    8192
#define F_IN      512
#define H_DIM     256
#define W_DIM     64
#define R_PER_BLK 16
#define NBLK      (N_ROWS / R_PER_BLK)   // 512
#define THREADS   256

// Per-block scalar partials (Wh already folded in): deterministic reduction.
__device__ float g_part[NBLK];

// ---- packed f32x2 helpers (sm_100+) ----
__device__ __forceinline__ unsigned long long fma2(unsigned long long a,
                                                   unsigned long long b,
                                                   unsigned long long c) {
    unsigned long long d;
    asm("fma.rn.f32x2 %0, %1, %2, %3;" : "=l"(d) : "l"(a), "l"(b), "l"(c));
    return d;
}
__device__ __forceinline__ unsigned long long pack2(float x) {
    unsigned long long d;
    unsigned int u = __float_as_uint(x);
    asm("mov.b64 %0, {%1, %1};" : "=l"(d) : "r"(u));
    return d;
}
__device__ __forceinline__ unsigned long long pack2f(float lo, float hi) {
    unsigned long long d;
    asm("mov.b64 %0, {%1, %2};" : "=l"(d) : "r"(__float_as_uint(lo)), "r"(__float_as_uint(hi)));
    return d;
}
__device__ __forceinline__ void unpack2(unsigned long long v, float& lo, float& hi) {
    unsigned int a, b;
    asm("mov.b64 {%0, %1}, %2;" : "=r"(a), "=r"(b) : "l"(v));
    lo = __uint_as_float(a);
    hi = __uint_as_float(b);
}

// Interleaved tile layouts (float index):
//   X tile (no swizzle):   addr = (k>>1)*32 + (r>>1)*4 + (k&1)*2 + (r&1)
//   enc tiles (swizzled):  addr = (k>>1)*32 + (((r>>1)^((k>>1)&7))&7)*4 + (k&1)*2 + (r&1)
// One 16B LDS at (kp*32 + slot*4) = { (2kp,2rp),(2kp,2rp+1),(2kp+1,2rp),(2kp+1,2rp+1) }
// i.e. ulonglong2{ f32x2 for k=2kp , f32x2 for k=2kp+1 }.

__global__ __launch_bounds__(THREADS, 4)
void fused_mlp_kernel(const float* __restrict__ X,
                      const float* __restrict__ W1, const float* __restrict__ b1,
                      const float* __restrict__ W2, const float* __restrict__ b2,
                      const float* __restrict__ Wq, const float* __restrict__ bq,
                      const float* __restrict__ Wh)
{
    __shared__ __align__(16) float sA[R_PER_BLK * F_IN];   // 32KB: X tile, later enc2
    __shared__ __align__(16) float sB[R_PER_BLK * H_DIM];  // 16KB: enc1, later partials

    const int t    = threadIdx.x;
    const int row0 = blockIdx.x * R_PER_BLK;

    // ---- Phase 0: load X tile into row-pair-interleaved layout ----
    // thread -> (r = t&15, float4 col c = (t>>4) + 16j). Coalesced-enough
    // (32B/row sectors fully used); smem writes <=2-way conflicted.
    {
        const int r  = t & 15;
        const int rp = r >> 1, rb = r & 1;
        const float4* Xg = reinterpret_cast<const float4*>(X + (size_t)(row0 + r) * F_IN);
        #pragma unroll
        for (int j = 0; j < 8; j++) {
            const int c   = (t >> 4) + 16 * j;    // 0..127
            const float4 v = Xg[c];
            const int kp0 = 2 * c;
            float* p = &sA[kp0 * 32 + rp * 4 + rb];
            p[0]      = v.x;   // k even
            p[2]      = v.y;   // k odd
            p[32]     = v.z;   // next kpair, k even
            p[34]     = v.w;   // next kpair, k odd
        }
    }
    __syncthreads();

    // ---- Phase 1: enc1 = relu(X @ W1 + b1); thread t owns column j=t ----
    {
        const int j = t;
        unsigned long long acc[8];
        const unsigned long long bj = pack2(b1[j]);
        #pragma unroll
        for (int rp = 0; rp < 8; rp++) acc[rp] = bj;

        #pragma unroll 4
        for (int kp = 0; kp < F_IN / 2; kp++) {
            const unsigned long long bw0 = pack2(W1[(2 * kp) * H_DIM + j]);
            const unsigned long long bw1 = pack2(W1[(2 * kp + 1) * H_DIM + j]);
            const ulonglong2* base = reinterpret_cast<const ulonglong2*>(&sA[kp * 32]);
            #pragma unroll
            for (int rp = 0; rp < 8; rp++) {
                ulonglong2 xv = base[rp];
                acc[rp] = fma2(xv.x, bw0, acc[rp]);
                acc[rp] = fma2(xv.y, bw1, acc[rp]);
            }
        }
        // store relu'd pairs into swizzled enc1 (region B)
        const int kp = j >> 1, kb = j & 1;
        #pragma unroll
        for (int rp = 0; rp < 8; rp++) {
            float lo, hi; unpack2(acc[rp], lo, hi);
            lo = fmaxf(lo, 0.0f); hi = fmaxf(hi, 0.0f);
            const int slot = (rp ^ (kp & 7)) & 7;
            *reinterpret_cast<float2*>(&sB[kp * 32 + slot * 4 + kb * 2]) = make_float2(lo, hi);
        }
    }
    __syncthreads();

    // ---- Phase 2: enc2 = relu(enc1 @ W2 + b2) -> region A ----
    {
        const int j = t;
        unsigned long long acc[8];
        const unsigned long long bj = pack2(b2[j]);
        #pragma unroll
        for (int rp = 0; rp < 8; rp++) acc[rp] = bj;

        #pragma unroll 4
        for (int kp = 0; kp < H_DIM / 2; kp++) {
            const unsigned long long bw0 = pack2(W2[(2 * kp) * H_DIM + j]);
            const unsigned long long bw1 = pack2(W2[(2 * kp + 1) * H_DIM + j]);
            const int ks = kp & 7;
            #pragma unroll
            for (int rp = 0; rp < 8; rp++) {
                const int slot = rp ^ ks;
                ulonglong2 xv = *reinterpret_cast<const ulonglong2*>(&sB[kp * 32 + slot * 4]);
                acc[rp] = fma2(xv.x, bw0, acc[rp]);
                acc[rp] = fma2(xv.y, bw1, acc[rp]);
            }
        }
        const int kp = j >> 1, kb = j & 1;
        #pragma unroll
        for (int rp = 0; rp < 8; rp++) {
            float lo, hi; unpack2(acc[rp], lo, hi);
            lo = fmaxf(lo, 0.0f); hi = fmaxf(hi, 0.0f);
            const int slot = (rp ^ (kp & 7)) & 7;
            *reinterpret_cast<float2*>(&sA[kp * 32 + slot * 4 + kb * 2]) = make_float2(lo, hi);
        }
    }
    __syncthreads();

    // ---- Phase 3: q = tanh(enc2 @ Wq + bq); per-block column sums ----
    {
        const int c  = t & (W_DIM - 1);   // 0..63
        const int rg = t >> 6;            // 0..3 -> row pairs 2rg, 2rg+1
        unsigned long long acc0, acc1;
        acc0 = acc1 = pack2(bq[c]);

        #pragma unroll 4
        for (int kp = 0; kp < H_DIM / 2; kp++) {
            const unsigned long long bw0 = pack2(Wq[(2 * kp) * W_DIM + c]);
            const unsigned long long bw1 = pack2(Wq[(2 * kp + 1) * W_DIM + c]);
            const int ks = kp & 7;
            const int s0 = (2 * rg)     ^ ks;
            const int s1 = (2 * rg + 1) ^ ks;
            ulonglong2 x0 = *reinterpret_cast<const ulonglong2*>(&sA[kp * 32 + s0 * 4]);
            ulonglong2 x1 = *reinterpret_cast<const ulonglong2*>(&sA[kp * 32 + s1 * 4]);
            acc0 = fma2(x0.x, bw0, acc0);
            acc0 = fma2(x0.y, bw1, acc0);
            acc1 = fma2(x1.x, bw0, acc1);
            acc1 = fma2(x1.y, bw1, acc1);
        }
        float a, b, cc, d;
        unpack2(acc0, a, b);
        unpack2(acc1, cc, d);
        const float s = tanhf(a) + tanhf(b) + tanhf(cc) + tanhf(d);
        sB[rg * W_DIM + c] = s;
    }
    __syncthreads();

    // ---- Epilogue: fold Wh -> one scalar per block ----
    __shared__ float s_warp[2];
    if (t < W_DIM) {
        float v = (sB[t] + sB[W_DIM + t]) + (sB[2 * W_DIM + t] + sB[3 * W_DIM + t]);
        v *= Wh[t];
        #pragma unroll
        for (int off = 16; off > 0; off >>= 1)
            v += __shfl_down_sync(0xffffffffu, v, off);
        if ((t & 31) == 0) s_warp[t >> 5] = v;
    }
    __syncthreads();
    if (t == 0) g_part[blockIdx.x] = s_warp[0] + s_warp[1];
}

// Sum 512 per-block scalars + bh -> out[0].
__global__ void reduce_kernel(const float* __restrict__ bh, float* __restrict__ out)
{
    __shared__ float sp[4];
    const int t = threadIdx.x;   // 128 threads
    float v = g_part[t] + g_part[t + 128] + g_part[t + 256] + g_part[t + 384];
    #pragma unroll
    for (int off = 16; off > 0; off >>= 1)
        v += __shfl_down_sync(0xffffffffu, v, off);
    if ((t & 31) == 0) sp[t >> 5] = v;
    __syncthreads();
    if (t == 0) out[0] = (sp[0] + sp[1]) + (sp[2] + sp[3]) + bh[0];
}

extern "C" void kernel_launch(void* const* d_in, const int* in_sizes, int n_in,
                              void* d_out, int out_size)
{
    const float* X  = (const float*)d_in[0];
    const float* W1 = (const float*)d_in[1];
    const float* b1 = (const float*)d_in[2];
    const float* W2 = (const float*)d_in[3];
    const float* b2 = (const float*)d_in[4];
    const float* Wq = (const float*)d_in[5];
    const float* bq = (const float*)d_in[6];
    const float* Wh = (const float*)d_in[7];
    const float* bh = (const float*)d_in[8];

    fused_mlp_kernel<<<NBLK, THREADS>>>(X, W1, b1, W2, b2, Wq, bq, Wh);
    reduce_kernel<<<1, 128>>>(bh, (float*)d_out);
}

// round 3
// speedup vs baseline: 1.1154x; 1.0009x over previous
#include <cuda_runtime.h>
#include <math.h>

#define N_ROWS    8192
#define F_IN      512
#define H_DIM     256
#define W_DIM     64
#define R_PER_BLK 16
#define NBLK      (N_ROWS / R_PER_BLK)   // 512
#define THREADS   256

// Per-block scalar partials (Wh already folded in): deterministic reduction.
__device__ float g_part[NBLK];

// ---- packed f32x2 helpers (sm_100+) ----
__device__ __forceinline__ unsigned long long fma2(unsigned long long a,
                                                   unsigned long long b,
                                                   unsigned long long c) {
    unsigned long long d;
    asm("fma.rn.f32x2 %0, %1, %2, %3;" : "=l"(d) : "l"(a), "l"(b), "l"(c));
    return d;
}
__device__ __forceinline__ unsigned long long pack2(float x) {
    unsigned long long d;
    unsigned int u = __float_as_uint(x);
    asm("mov.b64 %0, {%1, %1};" : "=l"(d) : "r"(u));
    return d;
}
__device__ __forceinline__ unsigned long long pack2f(float lo, float hi) {
    unsigned long long d;
    asm("mov.b64 %0, {%1, %2};" : "=l"(d) : "r"(__float_as_uint(lo)), "r"(__float_as_uint(hi)));
    return d;
}
__device__ __forceinline__ void unpack2(unsigned long long v, float& lo, float& hi) {
    unsigned int a, b;
    asm("mov.b64 {%0, %1}, %2;" : "=r"(a), "=r"(b) : "l"(v));
    lo = __uint_as_float(a);
    hi = __uint_as_float(b);
}

// Interleaved tile layouts (float index):
//   X tile (no swizzle):   addr = (k>>1)*32 + (r>>1)*4 + (k&1)*2 + (r&1)
//   enc tiles (swizzled):  addr = (k>>1)*32 + (((r>>1)^((k>>1)&7))&7)*4 + (k&1)*2 + (r&1)
// One 16B LDS at (kp*32 + slot*4) = { (2kp,2rp),(2kp,2rp+1),(2kp+1,2rp),(2kp+1,2rp+1) }
// i.e. ulonglong2{ f32x2 for k=2kp , f32x2 for k=2kp+1 }.

__global__ __launch_bounds__(THREADS, 4)
void fused_mlp_kernel(const float* __restrict__ X,
                      const float* __restrict__ W1, const float* __restrict__ b1,
                      const float* __restrict__ W2, const float* __restrict__ b2,
                      const float* __restrict__ Wq, const float* __restrict__ bq,
                      const float* __restrict__ Wh)
{
    __shared__ __align__(16) float sA[R_PER_BLK * F_IN];   // 32KB: X tile, later enc2
    __shared__ __align__(16) float sB[R_PER_BLK * H_DIM];  // 16KB: enc1, later partials

    const int t    = threadIdx.x;
    const int row0 = blockIdx.x * R_PER_BLK;

    // ---- Phase 0: load X tile into row-pair-interleaved layout ----
    // thread -> (r = t&15, float4 col c = (t>>4) + 16j). Coalesced-enough
    // (32B/row sectors fully used); smem writes <=2-way conflicted.
    {
        const int r  = t & 15;
        const int rp = r >> 1, rb = r & 1;
        const float4* Xg = reinterpret_cast<const float4*>(X + (size_t)(row0 + r) * F_IN);
        #pragma unroll
        for (int j = 0; j < 8; j++) {
            const int c   = (t >> 4) + 16 * j;    // 0..127
            const float4 v = Xg[c];
            const int kp0 = 2 * c;
            float* p = &sA[kp0 * 32 + rp * 4 + rb];
            p[0]      = v.x;   // k even
            p[2]      = v.y;   // k odd
            p[32]     = v.z;   // next kpair, k even
            p[34]     = v.w;   // next kpair, k odd
        }
    }
    __syncthreads();

    // ---- Phase 1: enc1 = relu(X @ W1 + b1); thread t owns column j=t ----
    {
        const int j = t;
        unsigned long long acc[8];
        const unsigned long long bj = pack2(b1[j]);
        #pragma unroll
        for (int rp = 0; rp < 8; rp++) acc[rp] = bj;

        #pragma unroll 4
        for (int kp = 0; kp < F_IN / 2; kp++) {
            const unsigned long long bw0 = pack2(W1[(2 * kp) * H_DIM + j]);
            const unsigned long long bw1 = pack2(W1[(2 * kp + 1) * H_DIM + j]);
            const ulonglong2* base = reinterpret_cast<const ulonglong2*>(&sA[kp * 32]);
            #pragma unroll
            for (int rp = 0; rp < 8; rp++) {
                ulonglong2 xv = base[rp];
                acc[rp] = fma2(xv.x, bw0, acc[rp]);
                acc[rp] = fma2(xv.y, bw1, acc[rp]);
            }
        }
        // store relu'd pairs into swizzled enc1 (region B)
        const int kp = j >> 1, kb = j & 1;
        #pragma unroll
        for (int rp = 0; rp < 8; rp++) {
            float lo, hi; unpack2(acc[rp], lo, hi);
            lo = fmaxf(lo, 0.0f); hi = fmaxf(hi, 0.0f);
            const int slot = (rp ^ (kp & 7)) & 7;
            *reinterpret_cast<float2*>(&sB[kp * 32 + slot * 4 + kb * 2]) = make_float2(lo, hi);
        }
    }
    __syncthreads();

    // ---- Phase 2: enc2 = relu(enc1 @ W2 + b2) -> region A ----
    {
        const int j = t;
        unsigned long long acc[8];
        const unsigned long long bj = pack2(b2[j]);
        #pragma unroll
        for (int rp = 0; rp < 8; rp++) acc[rp] = bj;

        #pragma unroll 4
        for (int kp = 0; kp < H_DIM / 2; kp++) {
            const unsigned long long bw0 = pack2(W2[(2 * kp) * H_DIM + j]);
            const unsigned long long bw1 = pack2(W2[(2 * kp + 1) * H_DIM + j]);
            const int ks = kp & 7;
            #pragma unroll
            for (int rp = 0; rp < 8; rp++) {
                const int slot = rp ^ ks;
                ulonglong2 xv = *reinterpret_cast<const ulonglong2*>(&sB[kp * 32 + slot * 4]);
                acc[rp] = fma2(xv.x, bw0, acc[rp]);
                acc[rp] = fma2(xv.y, bw1, acc[rp]);
            }
        }
        const int kp = j >> 1, kb = j & 1;
        #pragma unroll
        for (int rp = 0; rp < 8; rp++) {
            float lo, hi; unpack2(acc[rp], lo, hi);
            lo = fmaxf(lo, 0.0f); hi = fmaxf(hi, 0.0f);
            const int slot = (rp ^ (kp & 7)) & 7;
            *reinterpret_cast<float2*>(&sA[kp * 32 + slot * 4 + kb * 2]) = make_float2(lo, hi);
        }
    }
    __syncthreads();

    // ---- Phase 3: q = tanh(enc2 @ Wq + bq); per-block column sums ----
    {
        const int c  = t & (W_DIM - 1);   // 0..63
        const int rg = t >> 6;            // 0..3 -> row pairs 2rg, 2rg+1
        unsigned long long acc0, acc1;
        acc0 = acc1 = pack2(bq[c]);

        #pragma unroll 4
        for (int kp = 0; kp < H_DIM / 2; kp++) {
            const unsigned long long bw0 = pack2(Wq[(2 * kp) * W_DIM + c]);
            const unsigned long long bw1 = pack2(Wq[(2 * kp + 1) * W_DIM + c]);
            const int ks = kp & 7;
            const int s0 = (2 * rg)     ^ ks;
            const int s1 = (2 * rg + 1) ^ ks;
            ulonglong2 x0 = *reinterpret_cast<const ulonglong2*>(&sA[kp * 32 + s0 * 4]);
            ulonglong2 x1 = *reinterpret_cast<const ulonglong2*>(&sA[kp * 32 + s1 * 4]);
            acc0 = fma2(x0.x, bw0, acc0);
            acc0 = fma2(x0.y, bw1, acc0);
            acc1 = fma2(x1.x, bw0, acc1);
            acc1 = fma2(x1.y, bw1, acc1);
        }
        float a, b, cc, d;
        unpack2(acc0, a, b);
        unpack2(acc1, cc, d);
        const float s = tanhf(a) + tanhf(b) + tanhf(cc) + tanhf(d);
        sB[rg * W_DIM + c] = s;
    }
    __syncthreads();

    // ---- Epilogue: fold Wh -> one scalar per block ----
    __shared__ float s_warp[2];
    if (t < W_DIM) {
        float v = (sB[t] + sB[W_DIM + t]) + (sB[2 * W_DIM + t] + sB[3 * W_DIM + t]);
        v *= Wh[t];
        #pragma unroll
        for (int off = 16; off > 0; off >>= 1)
            v += __shfl_down_sync(0xffffffffu, v, off);
        if ((t & 31) == 0) s_warp[t >> 5] = v;
    }
    __syncthreads();
    if (t == 0) g_part[blockIdx.x] = s_warp[0] + s_warp[1];
}

// Sum 512 per-block scalars + bh -> out[0].
__global__ void reduce_kernel(const float* __restrict__ bh, float* __restrict__ out)
{
    __shared__ float sp[4];
    const int t = threadIdx.x;   // 128 threads
    float v = g_part[t] + g_part[t + 128] + g_part[t + 256] + g_part[t + 384];
    #pragma unroll
    for (int off = 16; off > 0; off >>= 1)
        v += __shfl_down_sync(0xffffffffu, v, off);
    if ((t & 31) == 0) sp[t >> 5] = v;
    __syncthreads();
    if (t == 0) out[0] = (sp[0] + sp[1]) + (sp[2] + sp[3]) + bh[0];
}

extern "C" void kernel_launch(void* const* d_in, const int* in_sizes, int n_in,
                              void* d_out, int out_size)
{
    const float* X  = (const float*)d_in[0];
    const float* W1 = (const float*)d_in[1];
    const float* b1 = (const float*)d_in[2];
    const float* W2 = (const float*)d_in[3];
    const float* b2 = (const float*)d_in[4];
    const float* Wq = (const float*)d_in[5];
    const float* bq = (const float*)d_in[6];
    const float* Wh = (const float*)d_in[7];
    const float* bh = (const float*)d_in[8];

    fused_mlp_kernel<<<NBLK, THREADS>>>(X, W1, b1, W2, b2, Wq, bq, Wh);
    reduce_kernel<<<1, 128>>>(bh, (float*)d_out);
}

// round 6
// speedup vs baseline: 2.0453x; 1.8337x over previous
#include <cuda_runtime.h>
#include <mma.h>
#include <math.h>
#include <stdint.h>

using namespace nvcuda;

#define NBLK    128        // CTAs, 64 rows each
#define THREADS 256
#define F_IN    512
#define H_DIM   256
#define W_DIM   64

#define LDX 40             // X chunk   [64][32]  pad->40
#define LDB 264            // W chunk   [32][256] pad->264
#define LDC 264            // act tiles [64][256] pad->264
#define LDQ 72             // Wq chunk  [32][64]  pad->72, also C3 [64][64]

// float offsets inside dynamic smem
#define O_X    0                    // 2 x 64*40   = 5120
#define O_B    5120                 // 2 x 32*264  = 16896
#define O_A1   22016                // 64*264      = 16896
#define O_A2   38912                // 64*264      = 16896
#define O_CON  55808                // b1(256) b2(256) bq(64) wh(64) red(8)
#define SMEMF  56456
#define SMEM_BYTES (SMEMF * 4)      // 225824 B

static __device__ float g_part[NBLK];

__device__ __forceinline__ float f2tf(float f) {   // round-to-nearest tf32
    uint32_t r;
    asm("cvt.rna.tf32.f32 %0, %1;" : "=r"(r) : "f"(f));
    return __uint_as_float(r);
}

typedef wmma::fragment<wmma::matrix_a, 16, 16, 8, wmma::precision::tf32, wmma::row_major> FragA;
typedef wmma::fragment<wmma::matrix_b, 16, 16, 8, wmma::precision::tf32, wmma::row_major> FragB;
typedef wmma::fragment<wmma::accumulator, 16, 16, 8, float> FragC;

__global__ void __launch_bounds__(THREADS, 1)
fused_wmma(const float* __restrict__ X,
           const float* __restrict__ W1, const float* __restrict__ b1,
           const float* __restrict__ W2, const float* __restrict__ b2,
           const float* __restrict__ Wq, const float* __restrict__ bq,
           const float* __restrict__ Wh)
{
    extern __shared__ float sm[];
    float* sX  = sm + O_X;
    float* sB  = sm + O_B;
    float* sA1 = sm + O_A1;
    float* sA2 = sm + O_A2;
    float* b1s = sm + O_CON;
    float* b2s = b1s + 256;
    float* bqs = b2s + 256;
    float* whs = bqs + 64;
    float* red = whs + 64;

    const int t = threadIdx.x;
    const int w = t >> 5;
    const int row0 = blockIdx.x * 64;
    const int mi = w >> 1;        // 0..3  (M-tile)
    const int nh = w & 1;         // 0..1  (N-half for L1/L2; N-pair for L3)

    // ---- consts ----
    b1s[t] = b1[t];
    b2s[t] = b2[t];
    if (t < 64) { bqs[t] = bq[t]; whs[t] = Wh[t]; }

    // ---- fill helpers ----
    auto fillX = [&](int s, int buf) {   // X chunk 64x32 -> sX[buf]
        float* dst = sX + buf * 2560;
        #pragma unroll
        for (int kq = 0; kq < 2; ++kq) {
            const int idx = t + kq * 256;          // 0..511 float4s
            const int r = idx >> 3, c4 = idx & 7;
            float4 v = *reinterpret_cast<const float4*>(X + (size_t)(row0 + r) * F_IN + s * 32 + c4 * 4);
            float4 o = make_float4(f2tf(v.x), f2tf(v.y), f2tf(v.z), f2tf(v.w));
            *reinterpret_cast<float4*>(dst + r * LDX + c4 * 4) = o;
        }
    };
    auto fillW = [&](const float* __restrict__ W, int s, int buf) {  // 32x256 -> sB[buf]
        float* dst = sB + buf * 8448;
        #pragma unroll
        for (int kq = 0; kq < 8; ++kq) {
            const int idx = t + kq * 256;          // 0..2047 float4s
            const int r = idx >> 6, c4 = idx & 63;
            float4 v = *reinterpret_cast<const float4*>(W + (size_t)(s * 32 + r) * H_DIM + c4 * 4);
            float4 o = make_float4(f2tf(v.x), f2tf(v.y), f2tf(v.z), f2tf(v.w));
            *reinterpret_cast<float4*>(dst + r * LDB + c4 * 4) = o;
        }
    };
    auto fillWq = [&](int s, int buf) {  // 32x64 -> sB[buf] with LDQ (FIXED mapping)
        float* dst = sB + buf * 8448;
        #pragma unroll
        for (int kq = 0; kq < 2; ++kq) {
            const int idx = t + kq * 256;          // 0..511 float4s = 32 rows x 16 f4
            const int r = idx >> 4, c4 = idx & 15;
            float4 v = *reinterpret_cast<const float4*>(Wq + (size_t)(s * 32 + r) * W_DIM + c4 * 4);
            float4 o = make_float4(f2tf(v.x), f2tf(v.y), f2tf(v.z), f2tf(v.w));
            *reinterpret_cast<float4*>(dst + r * LDQ + c4 * 4) = o;
        }
    };

    // ================= Layer 1: C1 = X @ W1  (K=512) =================
    FragC acc[8];
    #pragma unroll
    for (int j = 0; j < 8; ++j) wmma::fill_fragment(acc[j], 0.0f);

    fillX(0, 0); fillW(W1, 0, 0);
    __syncthreads();
    for (int s = 0; s < 16; ++s) {
        const int cb = s & 1;
        if (s < 15) { fillX(s + 1, (s + 1) & 1); fillW(W1, s + 1, (s + 1) & 1); }
        const float* ax = sX + cb * 2560;
        const float* bx = sB + cb * 8448;
        #pragma unroll
        for (int kk = 0; kk < 32; kk += 8) {
            FragA a;
            wmma::load_matrix_sync(a, ax + mi * 16 * LDX + kk, LDX);
            #pragma unroll
            for (int j = 0; j < 8; ++j) {
                FragB b;
                wmma::load_matrix_sync(b, bx + kk * LDB + (nh * 8 + j) * 16, LDB);
                wmma::mma_sync(acc[j], a, b, acc[j]);
            }
        }
        __syncthreads();
    }
    #pragma unroll
    for (int j = 0; j < 8; ++j)
        wmma::store_matrix_sync(sA1 + mi * 16 * LDC + (nh * 8 + j) * 16, acc[j], LDC, wmma::mem_row_major);
    __syncthreads();
    #pragma unroll
    for (int i = 0; i < 64; ++i) {      // relu + b1, tf32-round in place
        const int idx = t + i * 256;
        const int r = idx >> 8, c = idx & 255;
        sA1[r * LDC + c] = f2tf(fmaxf(sA1[r * LDC + c] + b1s[c], 0.0f));
    }
    __syncthreads();

    // ================= Layer 2: C2 = act1 @ W2  (K=256) =================
    #pragma unroll
    for (int j = 0; j < 8; ++j) wmma::fill_fragment(acc[j], 0.0f);
    fillW(W2, 0, 0);
    __syncthreads();
    for (int s = 0; s < 8; ++s) {
        const int cb = s & 1;
        if (s < 7) fillW(W2, s + 1, (s + 1) & 1);
        const float* bx = sB + cb * 8448;
        #pragma unroll
        for (int kk = 0; kk < 32; kk += 8) {
            FragA a;
            wmma::load_matrix_sync(a, sA1 + mi * 16 * LDC + s * 32 + kk, LDC);
            #pragma unroll
            for (int j = 0; j < 8; ++j) {
                FragB b;
                wmma::load_matrix_sync(b, bx + kk * LDB + (nh * 8 + j) * 16, LDB);
                wmma::mma_sync(acc[j], a, b, acc[j]);
            }
        }
        __syncthreads();
    }
    #pragma unroll
    for (int j = 0; j < 8; ++j)
        wmma::store_matrix_sync(sA2 + mi * 16 * LDC + (nh * 8 + j) * 16, acc[j], LDC, wmma::mem_row_major);
    __syncthreads();
    #pragma unroll
    for (int i = 0; i < 64; ++i) {      // relu + b2
        const int idx = t + i * 256;
        const int r = idx >> 8, c = idx & 255;
        sA2[r * LDC + c] = f2tf(fmaxf(sA2[r * LDC + c] + b2s[c], 0.0f));
    }
    __syncthreads();

    // ================= Layer 3: C3 = act2 @ Wq  (K=256, N=64) =================
    FragC a3[2];
    wmma::fill_fragment(a3[0], 0.0f);
    wmma::fill_fragment(a3[1], 0.0f);
    fillWq(0, 0);
    __syncthreads();
    for (int s = 0; s < 8; ++s) {
        const int cb = s & 1;
        if (s < 7) fillWq(s + 1, (s + 1) & 1);
        const float* bx = sB + cb * 8448;
        #pragma unroll
        for (int kk = 0; kk < 32; kk += 8) {
            FragA a;
            wmma::load_matrix_sync(a, sA2 + mi * 16 * LDC + s * 32 + kk, LDC);
            #pragma unroll
            for (int j = 0; j < 2; ++j) {
                FragB b;
                wmma::load_matrix_sync(b, bx + kk * LDQ + (nh * 2 + j) * 16, LDQ);
                wmma::mma_sync(a3[j], a, b, a3[j]);
            }
        }
        __syncthreads();
    }
    #pragma unroll
    for (int j = 0; j < 2; ++j)
        wmma::store_matrix_sync(sA1 + mi * 16 * LDQ + (nh * 2 + j) * 16, a3[j], LDQ, wmma::mem_row_major);
    __syncthreads();

    // ---- Epilogue: sum_{r,c} tanh(C3 + bq[c]) * Wh[c]  -> per-CTA scalar ----
    float p = 0.0f;
    {
        const int r  = t & 63;
        const int c0 = (t >> 6) * 16;
        #pragma unroll
        for (int c = 0; c < 16; ++c)
            p += tanhf(sA1[r * LDQ + c0 + c] + bqs[c0 + c]) * whs[c0 + c];
    }
    #pragma unroll
    for (int off = 16; off > 0; off >>= 1)
        p += __shfl_down_sync(0xffffffffu, p, off);
    if ((t & 31) == 0) red[w] = p;
    __syncthreads();
    if (t == 0) {
        float s = 0.0f;
        #pragma unroll
        for (int i = 0; i < 8; ++i) s += red[i];
        g_part[blockIdx.x] = s;
    }
}

// Sum 128 per-block scalars + bh -> out[0].
__global__ void reduce_kernel(const float* __restrict__ bh, float* __restrict__ out)
{
    __shared__ float sp[4];
    const int t = threadIdx.x;   // 128
    float v = g_part[t];
    #pragma unroll
    for (int off = 16; off > 0; off >>= 1)
        v += __shfl_down_sync(0xffffffffu, v, off);
    if ((t & 31) == 0) sp[t >> 5] = v;
    __syncthreads();
    if (t == 0) out[0] = (sp[0] + sp[1]) + (sp[2] + sp[3]) + bh[0];
}

extern "C" void kernel_launch(void* const* d_in, const int* in_sizes, int n_in,
                              void* d_out, int out_size)
{
    const float* X  = (const float*)d_in[0];
    const float* W1 = (const float*)d_in[1];
    const float* b1 = (const float*)d_in[2];
    const float* W2 = (const float*)d_in[3];
    const float* b2 = (const float*)d_in[4];
    const float* Wq = (const float*)d_in[5];
    const float* bq = (const float*)d_in[6];
    const float* Wh = (const float*)d_in[7];
    const float* bh = (const float*)d_in[8];

    cudaFuncSetAttribute(fused_wmma, cudaFuncAttributeMaxDynamicSharedMemorySize, SMEM_BYTES);
    fused_wmma<<<NBLK, THREADS, SMEM_BYTES>>>(X, W1, b1, W2, b2, Wq, bq, Wh);
    reduce_kernel<<<1, 128>>>(bh, (float*)d_out);
}

// round 7
// speedup vs baseline: 2.2204x; 1.0856x over previous
#include <cuda_runtime.h>
#include <mma.h>
#include <math.h>
#include <stdint.h>

using namespace nvcuda;

#define NBLK    128        // CTAs, 64 rows each
#define THREADS 256
#define F_IN    512
#define H_DIM   256
#define W_DIM   64

// pads chosen so gcd(LD,32)=4 -> 2-way max bank conflicts (was gcd=8 -> 4-way)
#define LDX 36             // X chunk   [64][32]
#define LDB 260            // W chunk   [32][256]
#define LDC 260            // act tiles [64][256]
#define LDQ 68             // Wq chunk  [32][64], also C3 [64][64]

// float offsets inside dynamic smem
#define O_X    0                    // 2 x 64*36  = 4608
#define O_B    4608                 // 2 x 32*260 = 16640
#define O_A1   21248                // 64*260     = 16640
#define O_A2   37888                // 64*260     = 16640
#define O_CON  54528                // b1(256) b2(256) bq(64) wh(64) red(8) flag
#define SMEMF  55184
#define SMEM_BYTES (SMEMF * 4)      // 220736 B

static __device__ float g_part[NBLK];
static __device__ unsigned int g_cnt = 0;

__device__ __forceinline__ float f2tf(float f) {   // round-to-nearest tf32
    uint32_t r;
    asm("cvt.rna.tf32.f32 %0, %1;" : "=r"(r) : "f"(f));
    return __uint_as_float(r);
}

typedef wmma::fragment<wmma::matrix_a, 16, 16, 8, wmma::precision::tf32, wmma::row_major> FragA;
typedef wmma::fragment<wmma::matrix_b, 16, 16, 8, wmma::precision::tf32, wmma::row_major> FragB;
typedef wmma::fragment<wmma::accumulator, 16, 16, 8, float> FragC;

__global__ void __launch_bounds__(THREADS, 1)
fused_wmma(const float* __restrict__ X,
           const float* __restrict__ W1, const float* __restrict__ b1,
           const float* __restrict__ W2, const float* __restrict__ b2,
           const float* __restrict__ Wq, const float* __restrict__ bq,
           const float* __restrict__ Wh, const float* __restrict__ bh,
           float* __restrict__ out)
{
    extern __shared__ float sm[];
    float* sX  = sm + O_X;
    float* sB  = sm + O_B;
    float* sA1 = sm + O_A1;
    float* sA2 = sm + O_A2;
    float* b1s = sm + O_CON;
    float* b2s = b1s + 256;
    float* bqs = b2s + 256;
    float* whs = bqs + 64;
    float* red = whs + 64;
    float* flg = red + 8;

    const int t = threadIdx.x;
    const int w = t >> 5;
    const int row0 = blockIdx.x * 64;
    const int mg = w >> 2;        // 0..1 : M-tiles {2mg, 2mg+1}
    const int ng = w & 3;         // 0..3 : 4 j-tiles (L1/L2), 1 j-tile (L3)

    // ---- consts ----
    b1s[t] = b1[t];
    b2s[t] = b2[t];
    if (t < 64) { bqs[t] = bq[t]; whs[t] = Wh[t]; }

    // ---- fill helpers ----
    auto fillX = [&](int s, int buf) {   // X chunk 64x32 -> sX[buf]
        float* dst = sX + buf * 2304;
        #pragma unroll
        for (int kq = 0; kq < 2; ++kq) {
            const int idx = t + kq * 256;          // 0..511 float4s
            const int r = idx >> 3, c4 = idx & 7;
            float4 v = *reinterpret_cast<const float4*>(X + (size_t)(row0 + r) * F_IN + s * 32 + c4 * 4);
            float4 o = make_float4(f2tf(v.x), f2tf(v.y), f2tf(v.z), f2tf(v.w));
            *reinterpret_cast<float4*>(dst + r * LDX + c4 * 4) = o;
        }
    };
    auto fillW = [&](const float* __restrict__ W, int s, int buf) {  // 32x256 -> sB[buf]
        float* dst = sB + buf * 8320;
        #pragma unroll
        for (int kq = 0; kq < 8; ++kq) {
            const int idx = t + kq * 256;          // 0..2047 float4s
            const int r = idx >> 6, c4 = idx & 63;
            float4 v = *reinterpret_cast<const float4*>(W + (size_t)(s * 32 + r) * H_DIM + c4 * 4);
            float4 o = make_float4(f2tf(v.x), f2tf(v.y), f2tf(v.z), f2tf(v.w));
            *reinterpret_cast<float4*>(dst + r * LDB + c4 * 4) = o;
        }
    };
    auto fillWq = [&](int s, int buf) {  // 32x64 -> sB[buf] with LDQ
        float* dst = sB + buf * 8320;
        #pragma unroll
        for (int kq = 0; kq < 2; ++kq) {
            const int idx = t + kq * 256;          // 0..511 float4s = 32 r x 16 f4
            const int r = idx >> 4, c4 = idx & 15;
            float4 v = *reinterpret_cast<const float4*>(Wq + (size_t)(s * 32 + r) * W_DIM + c4 * 4);
            float4 o = make_float4(f2tf(v.x), f2tf(v.y), f2tf(v.z), f2tf(v.w));
            *reinterpret_cast<float4*>(dst + r * LDQ + c4 * 4) = o;
        }
    };

    // ================= Layer 1: C1 = X @ W1  (K=512) =================
    FragC acc[2][4];
    #pragma unroll
    for (int i = 0; i < 2; ++i)
        #pragma unroll
        for (int j = 0; j < 4; ++j) wmma::fill_fragment(acc[i][j], 0.0f);

    fillX(0, 0); fillW(W1, 0, 0);
    __syncthreads();
    for (int s = 0; s < 16; ++s) {
        const int cb = s & 1;
        if (s < 15) { fillX(s + 1, (s + 1) & 1); fillW(W1, s + 1, (s + 1) & 1); }
        const float* ax = sX + cb * 2304;
        const float* bx = sB + cb * 8320;
        #pragma unroll
        for (int kk = 0; kk < 32; kk += 8) {
            FragA a[2];
            wmma::load_matrix_sync(a[0], ax + (mg * 2 + 0) * 16 * LDX + kk, LDX);
            wmma::load_matrix_sync(a[1], ax + (mg * 2 + 1) * 16 * LDX + kk, LDX);
            #pragma unroll
            for (int j = 0; j < 4; ++j) {
                FragB b;
                wmma::load_matrix_sync(b, bx + kk * LDB + (ng * 4 + j) * 16, LDB);
                wmma::mma_sync(acc[0][j], a[0], b, acc[0][j]);
                wmma::mma_sync(acc[1][j], a[1], b, acc[1][j]);
            }
        }
        __syncthreads();
    }
    #pragma unroll
    for (int i = 0; i < 2; ++i)
        #pragma unroll
        for (int j = 0; j < 4; ++j)
            wmma::store_matrix_sync(sA1 + (mg * 2 + i) * 16 * LDC + (ng * 4 + j) * 16,
                                    acc[i][j], LDC, wmma::mem_row_major);
    __syncthreads();
    #pragma unroll
    for (int i = 0; i < 64; ++i) {      // relu + b1, tf32-round in place
        const int idx = t + i * 256;
        const int r = idx >> 8, c = idx & 255;
        sA1[r * LDC + c] = f2tf(fmaxf(sA1[r * LDC + c] + b1s[c], 0.0f));
    }
    __syncthreads();

    // ================= Layer 2: C2 = act1 @ W2  (K=256) =================
    #pragma unroll
    for (int i = 0; i < 2; ++i)
        #pragma unroll
        for (int j = 0; j < 4; ++j) wmma::fill_fragment(acc[i][j], 0.0f);
    fillW(W2, 0, 0);
    __syncthreads();
    for (int s = 0; s < 8; ++s) {
        const int cb = s & 1;
        if (s < 7) fillW(W2, s + 1, (s + 1) & 1);
        const float* bx = sB + cb * 8320;
        #pragma unroll
        for (int kk = 0; kk < 32; kk += 8) {
            FragA a[2];
            wmma::load_matrix_sync(a[0], sA1 + (mg * 2 + 0) * 16 * LDC + s * 32 + kk, LDC);
            wmma::load_matrix_sync(a[1], sA1 + (mg * 2 + 1) * 16 * LDC + s * 32 + kk, LDC);
            #pragma unroll
            for (int j = 0; j < 4; ++j) {
                FragB b;
                wmma::load_matrix_sync(b, bx + kk * LDB + (ng * 4 + j) * 16, LDB);
                wmma::mma_sync(acc[0][j], a[0], b, acc[0][j]);
                wmma::mma_sync(acc[1][j], a[1], b, acc[1][j]);
            }
        }
        __syncthreads();
    }
    #pragma unroll
    for (int i = 0; i < 2; ++i)
        #pragma unroll
        for (int j = 0; j < 4; ++j)
            wmma::store_matrix_sync(sA2 + (mg * 2 + i) * 16 * LDC + (ng * 4 + j) * 16,
                                    acc[i][j], LDC, wmma::mem_row_major);
    __syncthreads();
    #pragma unroll
    for (int i = 0; i < 64; ++i) {      // relu + b2
        const int idx = t + i * 256;
        const int r = idx >> 8, c = idx & 255;
        sA2[r * LDC + c] = f2tf(fmaxf(sA2[r * LDC + c] + b2s[c], 0.0f));
    }
    __syncthreads();

    // ================= Layer 3: C3 = act2 @ Wq  (K=256, N=64) =================
    FragC a3[2];
    wmma::fill_fragment(a3[0], 0.0f);
    wmma::fill_fragment(a3[1], 0.0f);
    fillWq(0, 0);
    __syncthreads();
    for (int s = 0; s < 8; ++s) {
        const int cb = s & 1;
        if (s < 7) fillWq(s + 1, (s + 1) & 1);
        const float* bx = sB + cb * 8320;
        #pragma unroll
        for (int kk = 0; kk < 32; kk += 8) {
            FragA a[2];
            wmma::load_matrix_sync(a[0], sA2 + (mg * 2 + 0) * 16 * LDC + s * 32 + kk, LDC);
            wmma::load_matrix_sync(a[1], sA2 + (mg * 2 + 1) * 16 * LDC + s * 32 + kk, LDC);
            FragB b;
            wmma::load_matrix_sync(b, bx + kk * LDQ + ng * 16, LDQ);
            wmma::mma_sync(a3[0], a[0], b, a3[0]);
            wmma::mma_sync(a3[1], a[1], b, a3[1]);
        }
        __syncthreads();
    }
    #pragma unroll
    for (int i = 0; i < 2; ++i)
        wmma::store_matrix_sync(sA1 + (mg * 2 + i) * 16 * LDQ + ng * 16,
                                a3[i], LDQ, wmma::mem_row_major);
    __syncthreads();

    // ---- Epilogue: sum_{r,c} tanh(C3 + bq[c]) * Wh[c]  -> per-CTA scalar ----
    float p = 0.0f;
    {
        const int r  = t & 63;
        const int c0 = (t >> 6) * 16;
        #pragma unroll
        for (int c = 0; c < 16; ++c)
            p += tanhf(sA1[r * LDQ + c0 + c] + bqs[c0 + c]) * whs[c0 + c];
    }
    #pragma unroll
    for (int off = 16; off > 0; off >>= 1)
        p += __shfl_down_sync(0xffffffffu, p, off);
    if ((t & 31) == 0) red[w] = p;
    __syncthreads();
    if (t == 0) {
        float s = 0.0f;
        #pragma unroll
        for (int i = 0; i < 8; ++i) s += red[i];
        g_part[blockIdx.x] = s;
        __threadfence();
        unsigned int v = atomicAdd(&g_cnt, 1u);
        flg[0] = (v == NBLK - 1) ? 1.0f : 0.0f;
    }
    __syncthreads();

    // ---- Last CTA: final reduction (fixed order -> deterministic) ----
    if (flg[0] != 0.0f) {
        __threadfence();
        float v = 0.0f;
        if (t < 128) v = g_part[t];
        #pragma unroll
        for (int off = 16; off > 0; off >>= 1)
            v += __shfl_down_sync(0xffffffffu, v, off);
        if ((t & 31) == 0) red[w] = v;    // warps 0..3 hold partials
        __syncthreads();
        if (t == 0) {
            out[0] = (red[0] + red[1]) + (red[2] + red[3]) + bh[0];
            g_cnt = 0;                    // reset for next graph replay
        }
    }
}

extern "C" void kernel_launch(void* const* d_in, const int* in_sizes, int n_in,
                              void* d_out, int out_size)
{
    const float* X  = (const float*)d_in[0];
    const float* W1 = (const float*)d_in[1];
    const float* b1 = (const float*)d_in[2];
    const float* W2 = (const float*)d_in[3];
    const float* b2 = (const float*)d_in[4];
    const float* Wq = (const float*)d_in[5];
    const float* bq = (const float*)d_in[6];
    const float* Wh = (const float*)d_in[7];
    const float* bh = (const float*)d_in[8];

    cudaFuncSetAttribute(fused_wmma, cudaFuncAttributeMaxDynamicSharedMemorySize, SMEM_BYTES);
    fused_wmma<<<NBLK, THREADS, SMEM_BYTES>>>(X, W1, b1, W2, b2, Wq, bq, Wh, bh, (float*)d_out);
}